// round 1
// baseline (speedup 1.0000x reference)
#include <cuda_runtime.h>
#include <cstdint>

typedef unsigned long long u64;

#define HW 65536           // 256*256
#define NB 8               // batch
#define NC 32              // channels (Cin == Cout == 32)
#define NBC 256            // NB*NC

// Scratch: feat = channel-mixed activations [B, C, H, W], pooled 5x5 filters.
__device__ float g_feat[NB * NC * HW];
__device__ float g_filt[NBC * 25];

__device__ __forceinline__ u64 fma2(u64 a, u64 b, u64 c) {
    u64 d;
    asm("fma.rn.f32x2 %0, %1, %2, %3;" : "=l"(d) : "l"(a), "l"(b), "l"(c));
    return d;
}

// ---------------------------------------------------------------------------
// Kernel 1: channel mix (1x1 conv). Each thread computes one float2 pixel
// pair for all 32 output channels with packed f32x2 FMAs.
// grid = (32768/256, 8), block = 256
// ---------------------------------------------------------------------------
__global__ __launch_bounds__(256) void mix_kernel(
    const float* __restrict__ x,
    const float* __restrict__ w,
    const float* __restrict__ bias)
{
    __shared__ u64 sw[32 * 32];   // {w,w} duplicated pairs
    __shared__ u64 sb[32];

    int tid = threadIdx.x;
    for (int idx = tid; idx < 1024; idx += 256) {
        unsigned u = __float_as_uint(w[idx]);
        sw[idx] = ((u64)u << 32) | (u64)u;
    }
    if (tid < 32) {
        unsigned u = __float_as_uint(bias[tid]);
        sb[tid] = ((u64)u << 32) | (u64)u;
    }
    __syncthreads();

    int b = blockIdx.y;
    int pix2 = blockIdx.x * 256 + tid;           // float2 index within image
    const u64* xb = (const u64*)x + (size_t)b * (32u * (HW / 2)) + pix2;

    u64 acc[32];
#pragma unroll
    for (int o = 0; o < 32; o++) acc[o] = sb[o];

#pragma unroll 4
    for (int i = 0; i < 32; i++) {
        u64 xv = xb[i * (HW / 2)];
#pragma unroll
        for (int o = 0; o < 32; o++)
            acc[o] = fma2(sw[o * 32 + i], xv, acc[o]);
    }

    u64* fb = (u64*)g_feat + (size_t)b * (32u * (HW / 2)) + pix2;
#pragma unroll
    for (int o = 0; o < 32; o++) fb[o * (HW / 2)] = acc[o];
}

// ---------------------------------------------------------------------------
// Kernel 2: adaptive avg pool 256x256 -> 5x5 per (b,c).
// Bins (both axes): [0,52) [51,103) [102,154) [153,205) [204,256), size 52.
// One block per (b,c); thread t walks column w=t (coalesced across warp).
// grid = 256, block = 256
// ---------------------------------------------------------------------------
__global__ __launch_bounds__(256) void pool_kernel()
{
    __shared__ float pool[25];
    int bc = blockIdx.x;
    int w = threadIdx.x;
    if (w < 25) pool[w] = 0.0f;
    __syncthreads();

    const float* img = g_feat + (size_t)bc * HW;

    float cs0 = 0.f, cs1 = 0.f, cs2 = 0.f, cs3 = 0.f, cs4 = 0.f;
#pragma unroll
    for (int h = 0; h < 256; h++) {
        float v = img[h * 256 + w];
        if (h < 52)              cs0 += v;
        if (h >= 51 && h < 103)  cs1 += v;
        if (h >= 102 && h < 154) cs2 += v;
        if (h >= 153 && h < 205) cs3 += v;
        if (h >= 204)            cs4 += v;
    }
    float cs[5] = {cs0, cs1, cs2, cs3, cs4};

#pragma unroll
    for (int l = 0; l < 5; l++) {
        int s = (l * 256) / 5;
        int e = ((l + 1) * 256 + 4) / 5;   // ceil
        if (w >= s && w < e) {
#pragma unroll
            for (int k = 0; k < 5; k++)
                atomicAdd(&pool[k * 5 + l], cs[k]);
        }
    }
    __syncthreads();
    if (w < 25)
        g_filt[bc * 25 + w] = pool[w] * (1.0f / 2704.0f);   // 52*52
}

// ---------------------------------------------------------------------------
// Kernel 3: depthwise 5x5 'same' cross-correlation with per-(b,c) filter.
// Tile 64(w) x 32(h) outputs per block; 36x68 SMEM halo tile; each thread
// computes an 8-high column of outputs via a 12-row sliding window
// (60 LDS per 200 FMAs).
// grid = (32, 256), block = 256
// ---------------------------------------------------------------------------
__global__ __launch_bounds__(256) void conv_kernel(float* __restrict__ out)
{
    __shared__ float sh[36][68];

    int bc = blockIdx.y;
    int tile = blockIdx.x;
    int tx0 = (tile & 3) * 64;
    int ty0 = (tile >> 2) * 32;

    const float* img = g_feat + (size_t)bc * HW;

    // Load filter into registers (broadcast, L1-cached).
    float f[25];
#pragma unroll
    for (int t = 0; t < 25; t++) f[t] = g_filt[bc * 25 + t];

    // Load 36x68 input tile with zero padding at image borders.
    for (int idx = threadIdx.x; idx < 36 * 68; idx += 256) {
        int r = idx / 68;
        int c = idx - r * 68;
        int gy = ty0 + r - 2;
        int gx = tx0 + c - 2;
        float v = 0.0f;
        if ((unsigned)gy < 256u && (unsigned)gx < 256u)
            v = img[gy * 256 + gx];
        sh[r][c] = v;
    }
    __syncthreads();

    int x = threadIdx.x & 63;            // output column within tile
    int ys = (threadIdx.x >> 6) * 8;     // first output row within tile

    float acc[8];
#pragma unroll
    for (int j = 0; j < 8; j++) acc[j] = 0.0f;

#pragma unroll
    for (int r = 0; r < 12; r++) {       // input rows ys .. ys+11
        float v0 = sh[ys + r][x + 0];
        float v1 = sh[ys + r][x + 1];
        float v2 = sh[ys + r][x + 2];
        float v3 = sh[ys + r][x + 3];
        float v4 = sh[ys + r][x + 4];
#pragma unroll
        for (int ky = 0; ky < 5; ky++) {
            int j = r - ky;              // output row this input row feeds
            if (j >= 0 && j < 8) {
                acc[j] += v0 * f[ky * 5 + 0];
                acc[j] += v1 * f[ky * 5 + 1];
                acc[j] += v2 * f[ky * 5 + 2];
                acc[j] += v3 * f[ky * 5 + 3];
                acc[j] += v4 * f[ky * 5 + 4];
            }
        }
    }

    float* op = out + (size_t)bc * HW + (ty0 + ys) * 256 + tx0 + x;
#pragma unroll
    for (int j = 0; j < 8; j++)
        op[j * 256] = acc[j];
}

// ---------------------------------------------------------------------------
extern "C" void kernel_launch(void* const* d_in, const int* in_sizes, int n_in,
                              void* d_out, int out_size)
{
    const float* x    = (const float*)d_in[0];   // [8, 32, 256, 256]
    const float* w    = (const float*)d_in[1];   // [32, 32]
    const float* bias = (const float*)d_in[2];   // [32]
    float* out = (float*)d_out;                  // [8, 32, 256, 256]

    mix_kernel<<<dim3(HW / 2 / 256, NB), 256>>>(x, w, bias);
    pool_kernel<<<NBC, 256>>>();
    conv_kernel<<<dim3(32, NBC), 256>>>(out);
}